// round 1
// baseline (speedup 1.0000x reference)
#include <cuda_runtime.h>
#include <cuda_bf16.h>

// Swin window attention, fully fused, fp32 with fma.rn.f32x2.
// B=64, H=W=56, C=256, window 7x7 (49 tokens), 8 heads x 32 dim.
// One block per window: 4096 blocks x 256 threads.

#define NUM_HEAD 8
#define HEAD_DIM 32
#define IN_DIM 256
#define WS 7
#define TOK 49          // tokens per window
#define XSS 260         // padded row stride for X / AttnOut (260 % 32 == 4; 4*260 % 32 == 16)

// shared memory layout (in floats)
#define SM_AO   0
#define SM_POS  (TOK * XSS)                    // 12740
#define SM_XS   (SM_POS + 176)                 // 12916
#define SM_WC   (SM_XS + TOK * XSS)            // 25656 (qkv weight chunk 64x96)
#define SM_QS   (SM_WC + 64 * 96)              // 31800
#define SM_KS   (SM_QS + TOK * 33)
#define SM_VS   (SM_KS + TOK * 33)
#define SM_S    (SM_VS + TOK * 33)             // 49x50 scores
#define SM_TOTAL (SM_S + TOK * 50)             // 39101 floats = 156404 bytes
// out-proj weight chunk (64x256) reuses the XS region in phase B
#define SM_WOUT SM_XS

__device__ __forceinline__ unsigned long long pack2(float lo, float hi) {
    unsigned long long r;
    asm("mov.b64 %0, {%1, %2};" : "=l"(r) : "f"(lo), "f"(hi));
    return r;
}
__device__ __forceinline__ float2 unpack2(unsigned long long v) {
    float2 f;
    asm("mov.b64 {%0, %1}, %2;" : "=f"(f.x), "=f"(f.y) : "l"(v));
    return f;
}
#define FMA2(d, a, b) asm("fma.rn.f32x2 %0, %1, %2, %0;" : "+l"(d) : "l"(a), "l"(b))

__global__ __launch_bounds__(256, 1)
void swin_attn_kernel(const float* __restrict__ x,
                      const float* __restrict__ pos,
                      const float* __restrict__ wqkv,
                      const float* __restrict__ bqkv,
                      const float* __restrict__ wout,
                      const float* __restrict__ bout,
                      float* __restrict__ out)
{
    extern __shared__ float sm[];
    float* AO  = sm + SM_AO;
    float* POS = sm + SM_POS;
    float* XS  = sm + SM_XS;
    float* WC  = sm + SM_WC;
    float* QS  = sm + SM_QS;
    float* KS  = sm + SM_KS;
    float* VS  = sm + SM_VS;
    float* S   = sm + SM_S;
    float* WOUTC = sm + SM_WOUT;

    const int tid = threadIdx.x;
    const int win = blockIdx.x;          // 0..4095
    const int b  = win >> 6;
    const int wh = (win >> 3) & 7;
    const int ww = win & 7;
    const int ty = tid >> 4;             // 0..15 -> 4 rows each
    const int tx = tid & 15;             // 0..15 -> col pairs

    const float* xwin = x + (((long)b * 56 + wh * 7) * 56 + ww * 7) * IN_DIM;

    // ---- load pos embedding (13x13) ----
    for (int i = tid; i < 169; i += 256) POS[i] = pos[i];

    // ---- load X window: 49 rows x 64 float4 ----
    for (int q = tid; q < TOK * 64; q += 256) {
        int t = q >> 6, f = q & 63;
        int gi = t / 7, gj = t % 7;
        float4 v = *(const float4*)(xwin + (long)(gi * 56 + gj) * IN_DIM + f * 4);
        float* d = XS + t * XSS + f * 4;
        d[0] = v.x; d[1] = v.y; d[2] = v.z; d[3] = v.w;
    }
    __syncthreads();

    const float scl = 5.656854249492381f;  // sqrt(32)

    // ================= per-head: QKV GEMM + attention =================
    for (int h = 0; h < NUM_HEAD; h++) {
        unsigned long long acc[4][3];
        #pragma unroll
        for (int i = 0; i < 4; i++)
            #pragma unroll
            for (int j = 0; j < 3; j++) acc[i][j] = 0ULL;

        for (int kc = 0; kc < 4; kc++) {
            // stage wqkv chunk: rows kc*64..+63, cols {s*256 + h*32 + d} -> WC[r][32*s + d]
            for (int q = tid; q < 64 * 24; q += 256) {
                int r = q / 24, rem = q % 24, j = rem >> 3, f = rem & 7;
                float4 v = *(const float4*)(wqkv + (long)(kc * 64 + r) * 768 + j * 256 + h * 32 + f * 4);
                float* d = WC + r * 96 + j * 32 + f * 4;
                d[0] = v.x; d[1] = v.y; d[2] = v.z; d[3] = v.w;
            }
            __syncthreads();

            const float* xbase = XS + kc * 64;
            #pragma unroll 8
            for (int k = 0; k < 64; k++) {
                unsigned long long a2[4];
                #pragma unroll
                for (int i = 0; i < 4; i++) {
                    float a = xbase[(ty * 4 + i) * XSS + k];
                    a2[i] = pack2(a, a);
                }
                const float* wrow = WC + k * 96 + 2 * tx;
                #pragma unroll
                for (int j = 0; j < 3; j++) {
                    float2 bv = *(const float2*)(wrow + 32 * j);
                    unsigned long long b2 = pack2(bv.x, bv.y);
                    #pragma unroll
                    for (int i = 0; i < 4; i++) FMA2(acc[i][j], a2[i], b2);
                }
            }
            __syncthreads();
        }

        // write q/k/v (+ bias) into per-head smem buffers
        #pragma unroll
        for (int i = 0; i < 4; i++) {
            int row = ty * 4 + i;
            if (row < TOK) {
                #pragma unroll
                for (int j = 0; j < 3; j++) {
                    float2 v = unpack2(acc[i][j]);
                    float* buf = (j == 0) ? QS : (j == 1) ? KS : VS;
                    int d = 2 * tx;
                    v.x += bqkv[j * 256 + h * 32 + d];
                    v.y += bqkv[j * 256 + h * 32 + d + 1];
                    buf[row * 33 + d]     = v.x;
                    buf[row * 33 + d + 1] = v.y;
                }
            }
        }
        __syncthreads();

        // ---- scores: S[r][c] = (q_r . k_c) * sqrt(32) + bias ----
        for (int idx = tid; idx < TOK * TOK; idx += 256) {
            int r = idx / TOK, c = idx % TOK;
            float s = 0.f;
            const float* qr = QS + r * 33;
            const float* kr = KS + c * 33;
            #pragma unroll
            for (int d = 0; d < HEAD_DIM; d++) s += qr[d] * kr[d];
            int br = r / 7 + r % 7;
            int bc = c / 7 + c % 7;
            S[r * 50 + c] = s * scl + POS[br * 13 + bc];
        }
        __syncthreads();

        // ---- softmax per row (warp per row) ----
        {
            int warp = tid >> 5, lane = tid & 31;
            for (int r = warp; r < TOK; r += 8) {
                float v0 = S[r * 50 + lane];
                float v1 = (lane + 32 < TOK) ? S[r * 50 + lane + 32] : -3.0e38f;
                float m = fmaxf(v0, v1);
                #pragma unroll
                for (int off = 16; off > 0; off >>= 1)
                    m = fmaxf(m, __shfl_xor_sync(0xffffffffu, m, off));
                float e0 = __expf(v0 - m);
                float e1 = (lane + 32 < TOK) ? __expf(v1 - m) : 0.f;
                float ss = e0 + e1;
                #pragma unroll
                for (int off = 16; off > 0; off >>= 1)
                    ss += __shfl_xor_sync(0xffffffffu, ss, off);
                float inv = 1.f / ss;
                S[r * 50 + lane] = e0 * inv;
                if (lane + 32 < TOK) S[r * 50 + lane + 32] = e1 * inv;
            }
        }
        __syncthreads();

        // ---- P . V -> AttnOut columns h*32..h*32+31 ----
        for (int idx = tid; idx < TOK * HEAD_DIM; idx += 256) {
            int r = idx >> 5, d = idx & 31;
            float o = 0.f;
            const float* sr = S + r * 50;
            #pragma unroll 7
            for (int l = 0; l < TOK; l++) o += sr[l] * VS[l * 33 + d];
            AO[r * XSS + h * 32 + d] = o;
        }
        __syncthreads();
    }

    // ================= phase B: out = AttnOut @ w_out + b_out =================
    unsigned long long accB[4][8];
    #pragma unroll
    for (int i = 0; i < 4; i++)
        #pragma unroll
        for (int m = 0; m < 8; m++) accB[i][m] = 0ULL;

    for (int kc = 0; kc < 4; kc++) {
        __syncthreads();
        for (int q = tid; q < 64 * 64; q += 256) {   // 64 rows x 64 float4
            int r = q >> 6, f = q & 63;
            float4 v = *(const float4*)(wout + (long)(kc * 64 + r) * 256 + f * 4);
            float* d = WOUTC + r * 256 + f * 4;
            d[0] = v.x; d[1] = v.y; d[2] = v.z; d[3] = v.w;
        }
        __syncthreads();

        const float* abase = AO + kc * 64;
        #pragma unroll 4
        for (int k = 0; k < 64; k++) {
            unsigned long long a2[4];
            #pragma unroll
            for (int i = 0; i < 4; i++) {
                float a = abase[(ty * 4 + i) * XSS + k];
                a2[i] = pack2(a, a);
            }
            const float* wrow = WOUTC + k * 256 + 2 * tx;
            #pragma unroll
            for (int m = 0; m < 8; m++) {
                float2 bv = *(const float2*)(wrow + 32 * m);
                unsigned long long b2 = pack2(bv.x, bv.y);
                #pragma unroll
                for (int i = 0; i < 4; i++) FMA2(accB[i][m], a2[i], b2);
            }
        }
    }

    // ---- store ----
    #pragma unroll
    for (int i = 0; i < 4; i++) {
        int row = ty * 4 + i;
        if (row < TOK) {
            int gi = row / 7, gj = row % 7;
            float* o = out + (((long)b * 56 + wh * 7 + gi) * 56 + ww * 7 + gj) * 256;
            #pragma unroll
            for (int m = 0; m < 8; m++) {
                float2 v = unpack2(accB[i][m]);
                int c = 32 * m + 2 * tx;
                v.x += bout[c];
                v.y += bout[c + 1];
                *(float2*)(o + c) = v;
            }
        }
    }
}

extern "C" void kernel_launch(void* const* d_in, const int* in_sizes, int n_in,
                              void* d_out, int out_size)
{
    const float* x    = (const float*)d_in[0];
    const float* pos  = (const float*)d_in[1];
    const float* wqkv = (const float*)d_in[2];
    const float* bqkv = (const float*)d_in[3];
    const float* wout = (const float*)d_in[4];
    const float* bout = (const float*)d_in[5];
    float* out = (float*)d_out;

    const int smem_bytes = SM_TOTAL * sizeof(float);
    cudaFuncSetAttribute(swin_attn_kernel,
                         cudaFuncAttributeMaxDynamicSharedMemorySize, smem_bytes);
    swin_attn_kernel<<<4096, 256, smem_bytes>>>(x, pos, wqkv, bqkv, wout, bout, out);
}

// round 2
// speedup vs baseline: 1.5158x; 1.5158x over previous
#include <cuda_runtime.h>
#include <cuda_bf16.h>

// Swin window attention, fully fused, fp32 f32x2, 2 CTAs/SM.
// B=64, H=W=56, C=256, window 7x7 (49 tok), 8 heads x 32 dim.
// 4096 blocks x 256 threads. Out-projection fused per head into
// persistent register accumulators (no AttnOut smem buffer).

#define NUM_HEAD 8
#define HEAD_DIM 32
#define IN_DIM 256
#define TOK 49
#define XSS 258       // X row stride (even for f32x2; 4*258 % 32 = 8 -> conflict-free)
#define QSS 34        // Q/K/V/O row stride (even)
#define SSS 50        // score row stride

// shared layout (floats)
#define SM_XS   0
#define SM_W    12644                 // 49*258=12642 -> pad to 12644 (16B aligned)
#define SM_QS   (SM_W + 8192)        // 20836  (W region: max(64x96, 32x256)=8192)
#define SM_KS   (SM_QS + 1666)       // 22502
#define SM_VS   (SM_KS + 1666)       // 24168
#define SM_S    (SM_VS + 1666)       // 25834
#define SM_POS  (SM_S + 2450)        // 28284
#define SM_TOTAL 28456               // 113824 bytes -> 2 CTAs/SM

typedef unsigned long long u64;

__device__ __forceinline__ u64 splat2(float a) {
    u64 r;
    asm("mov.b64 %0, {%1, %1};" : "=l"(r) : "f"(a));
    return r;
}
__device__ __forceinline__ float2 unpack2(u64 v) {
    float2 f;
    asm("mov.b64 {%0, %1}, %2;" : "=f"(f.x), "=f"(f.y) : "l"(v));
    return f;
}
#define FMA2(d, a, b) asm("fma.rn.f32x2 %0, %1, %2, %0;" : "+l"(d) : "l"(a), "l"(b))

__global__ __launch_bounds__(256, 2)
void swin_attn_kernel(const float* __restrict__ x,
                      const float* __restrict__ pos,
                      const float* __restrict__ wqkv,
                      const float* __restrict__ bqkv,
                      const float* __restrict__ wout,
                      const float* __restrict__ bout,
                      float* __restrict__ out)
{
    extern __shared__ float sm[];
    float* XS  = sm + SM_XS;
    float* W   = sm + SM_W;    // union: qkv weight chunk (64x96) / wout head slab (32x256)
    float* QS  = sm + SM_QS;   // Q, later O (attn output per head)
    float* KS  = sm + SM_KS;
    float* VS  = sm + SM_VS;
    float* S   = sm + SM_S;
    float* POS = sm + SM_POS;

    const int tid = threadIdx.x;
    const int win = blockIdx.x;
    const int b  = win >> 6;
    const int wh = (win >> 3) & 7;
    const int ww = win & 7;
    const int ty = tid >> 4;           // 0..15 -> rows ty*4 .. ty*4+3
    const int tx = tid & 15;           // 0..15 -> float2 columns
    const int ty4 = ty * 4;

    const float* xwin = x + (((long)b * 56 + wh * 7) * 56 + ww * 7) * IN_DIM;

    for (int i = tid; i < 169; i += 256) POS[i] = pos[i];

    // load X window: 49 rows x 128 float2
    for (int q = tid; q < TOK * 128; q += 256) {
        int t = q >> 7, f = q & 127;
        int gi = t / 7, gj = t % 7;
        float2 v = *(const float2*)(xwin + (long)(gi * 56 + gj) * IN_DIM + 2 * f);
        *(float2*)(XS + t * XSS + 2 * f) = v;
    }

    const float scl = 5.656854249492381f;   // sqrt(32)

    // persistent output accumulators: rows ty4..ty4+3, cols 32*m + 2*tx
    u64 accB[4][8];
    #pragma unroll
    for (int i = 0; i < 4; i++)
        #pragma unroll
        for (int m = 0; m < 8; m++) accB[i][m] = 0ULL;

    for (int h = 0; h < NUM_HEAD; h++) {
        // ---------- QKV mini-GEMM: (49x256) @ (256x96) ----------
        u64 acc[4][3];
        #pragma unroll
        for (int i = 0; i < 4; i++)
            #pragma unroll
            for (int j = 0; j < 3; j++) acc[i][j] = 0ULL;

        for (int kc = 0; kc < 4; kc++) {
            __syncthreads();   // W region free (prev readers done)
            // stage wqkv rows kc*64..+63, cols {s*256+h*32+d} -> W[r][32*s+d]
            for (int q = tid; q < 64 * 24; q += 256) {
                int r = q / 24, rem = q % 24, j = rem >> 3, f = rem & 7;
                float4 v = *(const float4*)(wqkv + (long)(kc * 64 + r) * 768 + j * 256 + h * 32 + f * 4);
                float* d = W + r * 96 + j * 32 + f * 4;
                d[0] = v.x; d[1] = v.y; d[2] = v.z; d[3] = v.w;
            }
            __syncthreads();

            const float* xbase = XS + kc * 64;
            #pragma unroll 4
            for (int k = 0; k < 64; k += 2) {
                float2 av[4];
                #pragma unroll
                for (int i = 0; i < 4; i++)
                    av[i] = *(const float2*)(xbase + (ty4 + i) * XSS + k);
                u64 ax[4], ay[4];
                #pragma unroll
                for (int i = 0; i < 4; i++) { ax[i] = splat2(av[i].x); ay[i] = splat2(av[i].y); }
                #pragma unroll
                for (int j = 0; j < 3; j++) {
                    u64 b0 = *(const u64*)(W + k * 96 + 32 * j + 2 * tx);
                    u64 b1 = *(const u64*)(W + (k + 1) * 96 + 32 * j + 2 * tx);
                    #pragma unroll
                    for (int i = 0; i < 4; i++) {
                        FMA2(acc[i][j], ax[i], b0);
                        FMA2(acc[i][j], ay[i], b1);
                    }
                }
            }
        }

        // write Q/K/V (+bias)
        #pragma unroll
        for (int i = 0; i < 4; i++) {
            int row = ty4 + i;
            if (row < TOK) {
                #pragma unroll
                for (int j = 0; j < 3; j++) {
                    float2 v = unpack2(acc[i][j]);
                    float* buf = (j == 0) ? QS : (j == 1) ? KS : VS;
                    int d = 2 * tx;
                    v.x += bqkv[j * 256 + h * 32 + d];
                    v.y += bqkv[j * 256 + h * 32 + d + 1];
                    *(float2*)(buf + row * QSS + d) = v;
                }
            }
        }
        __syncthreads();

        // ---------- scores ----------
        for (int idx = tid; idx < TOK * TOK; idx += 256) {
            int r = idx / TOK, c = idx - r * TOK;
            const float* qr = QS + r * QSS;
            const float* kr = KS + c * QSS;
            u64 a2 = 0ULL;
            #pragma unroll
            for (int d = 0; d < 16; d++) {
                u64 qv = *(const u64*)(qr + 2 * d);
                u64 kv = *(const u64*)(kr + 2 * d);
                FMA2(a2, qv, kv);
            }
            float2 f = unpack2(a2);
            float s = f.x + f.y;
            int br = r / 7 + r % 7;
            int bc = c / 7 + c % 7;
            S[r * SSS + c] = s * scl + POS[br * 13 + bc];
        }
        __syncthreads();

        // ---------- softmax (warp per row) ----------
        {
            int warp = tid >> 5, lane = tid & 31;
            for (int r = warp; r < TOK; r += 8) {
                float v0 = S[r * SSS + lane];
                float v1 = (lane + 32 < TOK) ? S[r * SSS + lane + 32] : -3.0e38f;
                float m = fmaxf(v0, v1);
                #pragma unroll
                for (int off = 16; off > 0; off >>= 1)
                    m = fmaxf(m, __shfl_xor_sync(0xffffffffu, m, off));
                float e0 = __expf(v0 - m);
                float e1 = (lane + 32 < TOK) ? __expf(v1 - m) : 0.f;
                float ss = e0 + e1;
                #pragma unroll
                for (int off = 16; off > 0; off >>= 1)
                    ss += __shfl_xor_sync(0xffffffffu, ss, off);
                float inv = 1.f / ss;
                S[r * SSS + lane] = e0 * inv;
                if (lane + 32 < TOK) S[r * SSS + lane + 32] = e1 * inv;
            }
        }
        __syncthreads();

        // ---------- P @ V -> O (into QS, Q is dead) ----------
        // 25 row-pairs x 16 float2-cols
        for (int idx = tid; idx < 400; idx += 256) {
            int rp = idx >> 4, d2 = idx & 15;
            int r0 = rp * 2, r1 = r0 + 1;
            const float* s0 = S + r0 * SSS;
            const float* s1 = S + r1 * SSS;
            u64 o0 = 0ULL, o1 = 0ULL;
            #pragma unroll 7
            for (int l = 0; l < TOK; l++) {
                u64 vv = *(const u64*)(VS + l * QSS + 2 * d2);
                FMA2(o0, splat2(s0[l]), vv);
                FMA2(o1, splat2(s1[l]), vv);
            }
            *(float2*)(QS + r0 * QSS + 2 * d2) = unpack2(o0);
            if (r1 < TOK) *(float2*)(QS + r1 * QSS + 2 * d2) = unpack2(o1);
        }
        __syncthreads();

        // ---------- stage wout head slab: rows h*32..+31, all 256 cols ----------
        for (int q = tid; q < 32 * 64; q += 256) {
            int r = q >> 6, f = q & 63;
            float4 v = *(const float4*)(wout + (long)(h * 32 + r) * 256 + f * 4);
            float* d = W + r * 256 + f * 4;
            d[0] = v.x; d[1] = v.y; d[2] = v.z; d[3] = v.w;
        }
        __syncthreads();

        // ---------- out_acc += O @ W_h  (k = 32) ----------
        #pragma unroll 4
        for (int k = 0; k < 32; k += 2) {
            float2 av[4];
            #pragma unroll
            for (int i = 0; i < 4; i++)
                av[i] = *(const float2*)(QS + (ty4 + i) * QSS + k);
            u64 ax[4], ay[4];
            #pragma unroll
            for (int i = 0; i < 4; i++) { ax[i] = splat2(av[i].x); ay[i] = splat2(av[i].y); }
            #pragma unroll
            for (int m = 0; m < 8; m++) {
                u64 b0 = *(const u64*)(W + k * 256 + 32 * m + 2 * tx);
                u64 b1 = *(const u64*)(W + (k + 1) * 256 + 32 * m + 2 * tx);
                #pragma unroll
                for (int i = 0; i < 4; i++) {
                    FMA2(accB[i][m], ax[i], b0);
                    FMA2(accB[i][m], ay[i], b1);
                }
            }
        }
        // kc-loop top sync of next head protects W/QS reuse
    }

    // ---------- store ----------
    #pragma unroll
    for (int i = 0; i < 4; i++) {
        int row = ty4 + i;
        if (row < TOK) {
            int gi = row / 7, gj = row % 7;
            float* o = out + (((long)b * 56 + wh * 7 + gi) * 56 + ww * 7 + gj) * 256;
            #pragma unroll
            for (int m = 0; m < 8; m++) {
                float2 v = unpack2(accB[i][m]);
                int c = 32 * m + 2 * tx;
                v.x += bout[c];
                v.y += bout[c + 1];
                *(float2*)(o + c) = v;
            }
        }
    }
}

extern "C" void kernel_launch(void* const* d_in, const int* in_sizes, int n_in,
                              void* d_out, int out_size)
{
    const float* x    = (const float*)d_in[0];
    const float* pos  = (const float*)d_in[1];
    const float* wqkv = (const float*)d_in[2];
    const float* bqkv = (const float*)d_in[3];
    const float* wout = (const float*)d_in[4];
    const float* bout = (const float*)d_in[5];
    float* out = (float*)d_out;

    const int smem_bytes = SM_TOTAL * sizeof(float);
    cudaFuncSetAttribute(swin_attn_kernel,
                         cudaFuncAttributeMaxDynamicSharedMemorySize, smem_bytes);
    swin_attn_kernel<<<4096, 256, smem_bytes>>>(x, pos, wqkv, bqkv, wout, bout, out);
}

// round 3
// speedup vs baseline: 1.5659x; 1.0330x over previous
#include <cuda_runtime.h>
#include <cuda_bf16.h>

// Swin window attention, fully fused, fp32 f32x2, 2 CTAs/SM.
// R3: float4 A-loads (4-k units), transposed K for register-tiled scores,
// register-tiled P.V, wout staging folded into score phase.

#define NUM_HEAD 8
#define HEAD_DIM 32
#define IN_DIM 256
#define TOK 49
#define XSS 260       // X row stride (1040 B, 16B-aligned rows)
#define QSS 36        // Q/V/O row stride (144 B, 16B-aligned rows)
#define KTS 52        // K-transposed row stride
#define SSS 50        // score row stride

// shared layout (floats)
#define SM_XS   0
#define SM_W    12740                 // 49*260
#define SM_QS   (SM_W + 8192)        // 20932 (W: max(64x96, 32x256)=8192)
#define SM_VS   (SM_QS + 1764)       // 22696 (49*36)
#define SM_KT   (SM_VS + 1764)       // 24460 (32*52=1664)
#define SM_S    (SM_KT + 1664)       // 26124 (49*50=2450 -> pad 2452)
#define SM_POS  (SM_S + 2452)        // 28576
#define SM_TOTAL (SM_POS + 172)      // 28748 floats = 114992 B -> 2 CTAs/SM

typedef unsigned long long u64;

__device__ __forceinline__ u64 splat2(float a) {
    u64 r;
    asm("mov.b64 %0, {%1, %1};" : "=l"(r) : "f"(a));
    return r;
}
__device__ __forceinline__ float2 unpack2(u64 v) {
    float2 f;
    asm("mov.b64 {%0, %1}, %2;" : "=f"(f.x), "=f"(f.y) : "l"(v));
    return f;
}
#define FMA2(d, a, b) asm("fma.rn.f32x2 %0, %1, %2, %0;" : "+l"(d) : "l"(a), "l"(b))

__global__ __launch_bounds__(256, 2)
void swin_attn_kernel(const float* __restrict__ x,
                      const float* __restrict__ pos,
                      const float* __restrict__ wqkv,
                      const float* __restrict__ bqkv,
                      const float* __restrict__ wout,
                      const float* __restrict__ bout,
                      float* __restrict__ out)
{
    extern __shared__ float sm[];
    float* XS  = sm + SM_XS;
    float* W   = sm + SM_W;
    float* QS  = sm + SM_QS;   // Q, later O
    float* VS  = sm + SM_VS;
    float* KT  = sm + SM_KT;   // K transposed [32][52]
    float* S   = sm + SM_S;
    float* POS = sm + SM_POS;

    const int tid = threadIdx.x;
    const int win = blockIdx.x;
    const int b  = win >> 6;
    const int wh = (win >> 3) & 7;
    const int ww = win & 7;
    const int ty = tid >> 4;
    const int tx = tid & 15;
    const int ty4 = ty * 4;
    const int dx = 2 * tx;

    const float* xwin = x + (((long)b * 56 + wh * 7) * 56 + ww * 7) * IN_DIM;

    for (int i = tid; i < 169; i += 256) POS[i] = pos[i];

    // load X window: 49 rows x 64 float4
    for (int q = tid; q < TOK * 64; q += 256) {
        int t = q >> 6, f = q & 63;
        int gi = t / 7, gj = t % 7;
        float4 v = *(const float4*)(xwin + (long)(gi * 56 + gj) * IN_DIM + 4 * f);
        *(float4*)(XS + t * XSS + 4 * f) = v;
    }

    const float scl = 5.656854249492381f;   // sqrt(32)

    // persistent out-proj accumulators
    u64 accB[4][8];
    #pragma unroll
    for (int i = 0; i < 4; i++)
        #pragma unroll
        for (int m = 0; m < 8; m++) accB[i][m] = 0ULL;

    for (int h = 0; h < NUM_HEAD; h++) {
        // ================= QKV mini-GEMM: (49x256) @ (256x96) =================
        u64 acc[4][3];
        #pragma unroll
        for (int i = 0; i < 4; i++)
            #pragma unroll
            for (int j = 0; j < 3; j++) acc[i][j] = 0ULL;

        for (int kc = 0; kc < 4; kc++) {
            __syncthreads();   // W region free
            for (int q = tid; q < 64 * 24; q += 256) {
                int r = q / 24, rem = q % 24, j = rem >> 3, f = rem & 7;
                float4 v = *(const float4*)(wqkv + (long)(kc * 64 + r) * 768 + j * 256 + h * 32 + f * 4);
                float* d = W + r * 96 + j * 32 + f * 4;
                d[0] = v.x; d[1] = v.y; d[2] = v.z; d[3] = v.w;
            }
            __syncthreads();

            const float* xbase = XS + kc * 64;
            #pragma unroll 1
            for (int k = 0; k < 64; k += 4) {
                float af[4][4];
                #pragma unroll
                for (int i = 0; i < 4; i++) {
                    float4 t4 = *(const float4*)(xbase + (ty4 + i) * XSS + k);
                    af[i][0] = t4.x; af[i][1] = t4.y; af[i][2] = t4.z; af[i][3] = t4.w;
                }
                #pragma unroll
                for (int kk = 0; kk < 4; kk++) {
                    const float* wrow = W + (k + kk) * 96 + dx;
                    u64 b0 = *(const u64*)(wrow);
                    u64 b1 = *(const u64*)(wrow + 32);
                    u64 b2 = *(const u64*)(wrow + 64);
                    #pragma unroll
                    for (int i = 0; i < 4; i++) {
                        u64 a = splat2(af[i][kk]);
                        FMA2(acc[i][0], a, b0);
                        FMA2(acc[i][1], a, b1);
                        FMA2(acc[i][2], a, b2);
                    }
                }
            }
        }

        // write Q, K^T, V (+bias)
        {
            float bq0 = bqkv[h * 32 + dx],        bq1 = bqkv[h * 32 + dx + 1];
            float bk0 = bqkv[256 + h * 32 + dx],  bk1 = bqkv[256 + h * 32 + dx + 1];
            float bv0 = bqkv[512 + h * 32 + dx],  bv1 = bqkv[512 + h * 32 + dx + 1];
            #pragma unroll
            for (int i = 0; i < 4; i++) {
                int row = ty4 + i;
                if (row < TOK) {
                    float2 vq = unpack2(acc[i][0]);
                    vq.x += bq0; vq.y += bq1;
                    *(float2*)(QS + row * QSS + dx) = vq;
                    float2 vk = unpack2(acc[i][1]);
                    KT[dx * KTS + row]       = vk.x + bk0;
                    KT[(dx + 1) * KTS + row] = vk.y + bk1;
                    float2 vv = unpack2(acc[i][2]);
                    vv.x += bv0; vv.y += bv1;
                    *(float2*)(VS + row * QSS + dx) = vv;
                }
            }
        }
        __syncthreads();

        // ========== score phase + wout staging (W idle here) ==========
        for (int q = tid; q < 32 * 64; q += 256) {
            int r = q >> 6, f = q & 63;
            float4 v = *(const float4*)(wout + (long)(h * 32 + r) * 256 + f * 4);
            float* d = W + r * 256 + f * 4;
            d[0] = v.x; d[1] = v.y; d[2] = v.z; d[3] = v.w;
        }

        if (tid < 169) {
            int sy = tid / 13, sx = tid - sy * 13;
            int r0 = 4 * sy, c0 = 4 * sx;
            u64 sa[4][2];
            #pragma unroll
            for (int i = 0; i < 4; i++) { sa[i][0] = 0ULL; sa[i][1] = 0ULL; }

            #pragma unroll 4
            for (int d = 0; d < 32; d += 2) {
                u64 k0a = *(const u64*)(KT + d * KTS + c0);
                u64 k0b = *(const u64*)(KT + d * KTS + c0 + 2);
                u64 k1a = *(const u64*)(KT + (d + 1) * KTS + c0);
                u64 k1b = *(const u64*)(KT + (d + 1) * KTS + c0 + 2);
                #pragma unroll
                for (int i = 0; i < 4; i++) {
                    float2 qv = *(const float2*)(QS + (r0 + i) * QSS + d);
                    u64 qx = splat2(qv.x), qy = splat2(qv.y);
                    FMA2(sa[i][0], qx, k0a);
                    FMA2(sa[i][1], qx, k0b);
                    FMA2(sa[i][0], qy, k1a);
                    FMA2(sa[i][1], qy, k1b);
                }
            }
            #pragma unroll
            for (int i = 0; i < 4; i++) {
                int r = r0 + i;
                if (r < TOK) {
                    int br = r / 7 + r % 7;
                    #pragma unroll
                    for (int jc = 0; jc < 2; jc++) {
                        int c = c0 + 2 * jc;
                        if (c <= 48) {
                            float2 f = unpack2(sa[i][jc]);
                            int bc0 = c / 7 + c % 7;
                            int bc1 = (c + 1) / 7 + (c + 1) % 7;
                            f.x = f.x * scl + POS[br * 13 + bc0];
                            f.y = f.y * scl + POS[br * 13 + bc1];
                            *(float2*)(S + r * SSS + c) = f;
                        }
                    }
                }
            }
        }
        __syncthreads();

        // ========== softmax (warp per row) ==========
        {
            int warp = tid >> 5, lane = tid & 31;
            for (int r = warp; r < TOK; r += 8) {
                float v0 = S[r * SSS + lane];
                float v1 = (lane + 32 < TOK) ? S[r * SSS + lane + 32] : -3.0e38f;
                float m = fmaxf(v0, v1);
                #pragma unroll
                for (int off = 16; off > 0; off >>= 1)
                    m = fmaxf(m, __shfl_xor_sync(0xffffffffu, m, off));
                float e0 = __expf(v0 - m);
                float e1 = (lane + 32 < TOK) ? __expf(v1 - m) : 0.f;
                float ss = e0 + e1;
                #pragma unroll
                for (int off = 16; off > 0; off >>= 1)
                    ss += __shfl_xor_sync(0xffffffffu, ss, off);
                float inv = 1.f / ss;
                S[r * SSS + lane] = e0 * inv;
                if (lane + 32 < TOK) S[r * SSS + lane + 32] = e1 * inv;
            }
        }
        __syncthreads();

        // ========== P @ V -> O (into QS) ==========
        {
            int rr[4];
            #pragma unroll
            for (int i = 0; i < 4; i++) rr[i] = (ty4 + i < TOK) ? (ty4 + i) : 0;
            u64 o[4] = {0ULL, 0ULL, 0ULL, 0ULL};
            #pragma unroll 4
            for (int l = 0; l < 48; l += 2) {
                u64 v0 = *(const u64*)(VS + l * QSS + dx);
                u64 v1 = *(const u64*)(VS + (l + 1) * QSS + dx);
                #pragma unroll
                for (int i = 0; i < 4; i++) {
                    float2 sv = *(const float2*)(S + rr[i] * SSS + l);
                    FMA2(o[i], splat2(sv.x), v0);
                    FMA2(o[i], splat2(sv.y), v1);
                }
            }
            {   // tail l = 48
                u64 v48 = *(const u64*)(VS + 48 * QSS + dx);
                #pragma unroll
                for (int i = 0; i < 4; i++)
                    FMA2(o[i], splat2(S[rr[i] * SSS + 48]), v48);
            }
            #pragma unroll
            for (int i = 0; i < 4; i++)
                if (ty4 + i < TOK)
                    *(float2*)(QS + (ty4 + i) * QSS + dx) = unpack2(o[i]);
        }
        __syncthreads();

        // ========== out_acc += O @ W_h (k=32) ==========
        #pragma unroll 1
        for (int k = 0; k < 32; k += 4) {
            float af[4][4];
            #pragma unroll
            for (int i = 0; i < 4; i++) {
                float4 t4 = *(const float4*)(QS + (ty4 + i) * QSS + k);
                af[i][0] = t4.x; af[i][1] = t4.y; af[i][2] = t4.z; af[i][3] = t4.w;
            }
            #pragma unroll
            for (int kk = 0; kk < 4; kk++) {
                const float* wrow = W + (k + kk) * 256 + dx;
                #pragma unroll
                for (int m = 0; m < 8; m++) {
                    u64 bm = *(const u64*)(wrow + 32 * m);
                    #pragma unroll
                    for (int i = 0; i < 4; i++)
                        FMA2(accB[i][m], splat2(af[i][kk]), bm);
                }
            }
        }
        // next head's kc-top sync protects W/QS reuse
    }

    // ========== store ==========
    #pragma unroll
    for (int i = 0; i < 4; i++) {
        int row = ty4 + i;
        if (row < TOK) {
            int gi = row / 7, gj = row % 7;
            float* o = out + (((long)b * 56 + wh * 7 + gi) * 56 + ww * 7 + gj) * 256;
            #pragma unroll
            for (int m = 0; m < 8; m++) {
                float2 v = unpack2(accB[i][m]);
                int c = 32 * m + dx;
                v.x += bout[c];
                v.y += bout[c + 1];
                *(float2*)(o + c) = v;
            }
        }
    }
}

extern "C" void kernel_launch(void* const* d_in, const int* in_sizes, int n_in,
                              void* d_out, int out_size)
{
    const float* x    = (const float*)d_in[0];
    const float* pos  = (const float*)d_in[1];
    const float* wqkv = (const float*)d_in[2];
    const float* bqkv = (const float*)d_in[3];
    const float* wout = (const float*)d_in[4];
    const float* bout = (const float*)d_in[5];
    float* out = (float*)d_out;

    const int smem_bytes = SM_TOTAL * sizeof(float);
    cudaFuncSetAttribute(swin_attn_kernel,
                         cudaFuncAttributeMaxDynamicSharedMemorySize, smem_bytes);
    swin_attn_kernel<<<4096, 256, smem_bytes>>>(x, pos, wqkv, bqkv, wout, bout, out);
}

// round 5
// speedup vs baseline: 3.1590x; 2.0174x over previous
#include <cuda_runtime.h>
#include <cuda_bf16.h>
#include <cstdint>

// ============================================================
// Swin window attention pipeline, R5: mma.sync bf16-split GEMMs
// (tcgen05 unavailable: harness compiles via compute_103 virtual
//  arch, no 'a' features). Baseline-PTX HMMA + cp.async.
//   0) split x -> bf16 hi/lo ; split+transpose weights
//   1) qkv = x @ w_qkv + b_qkv        (mma.sync, 3-term split)
//   2) windowed attention (fp32) -> O hi/lo (bf16)
//   3) out = O @ w_out + b_out        (mma.sync, 3-term split)
// ============================================================

#define M_TOTAL 200704          // 64*56*56 = 1568 * 128
typedef unsigned long long u64;

// ---------------- device scratch ----------------
__device__ float g_qkv[(size_t)M_TOTAL * 768];              // 616 MB
__device__ __nv_bfloat16 g_x_hi[(size_t)M_TOTAL * 256];     // 103 MB
__device__ __nv_bfloat16 g_x_lo[(size_t)M_TOTAL * 256];
__device__ __nv_bfloat16 g_o_hi[(size_t)M_TOTAL * 256];
__device__ __nv_bfloat16 g_o_lo[(size_t)M_TOTAL * 256];
__device__ __nv_bfloat16 g_wq_hi[768 * 256];
__device__ __nv_bfloat16 g_wq_lo[768 * 256];
__device__ __nv_bfloat16 g_wo_hi[256 * 256];
__device__ __nv_bfloat16 g_wo_lo[256 * 256];

// ---------------- helpers ----------------
__device__ __forceinline__ uint32_t smem_u32(const void* p) {
    uint32_t a;
    asm("{ .reg .u64 t; cvta.to.shared.u64 t, %1; cvt.u32.u64 %0, t; }" : "=r"(a) : "l"(p));
    return a;
}
__device__ __forceinline__ void cpasync16(uint32_t dst, const void* src) {
    asm volatile("cp.async.cg.shared.global [%0], [%1], 16;" :: "r"(dst), "l"(src) : "memory");
}
#define CP_COMMIT() asm volatile("cp.async.commit_group;" ::: "memory")
#define CP_WAIT0()  asm volatile("cp.async.wait_group 0;" ::: "memory")

__device__ __forceinline__ void split1(float a, uint16_t& h, uint16_t& l) {
    __nv_bfloat16 hb = __float2bfloat16_rn(a);
    float hf = __bfloat162float(hb);
    __nv_bfloat16 lb = __float2bfloat16_rn(a - hf);
    h = __bfloat16_as_ushort(hb);
    l = __bfloat16_as_ushort(lb);
}

__device__ __forceinline__ void mma16816(float* c, const uint32_t* a, uint32_t b0, uint32_t b1) {
    asm volatile("mma.sync.aligned.m16n8k16.row.col.f32.bf16.bf16.f32 "
        "{%0,%1,%2,%3}, {%4,%5,%6,%7}, {%8,%9}, {%0,%1,%2,%3};"
        : "+f"(c[0]), "+f"(c[1]), "+f"(c[2]), "+f"(c[3])
        : "r"(a[0]), "r"(a[1]), "r"(a[2]), "r"(a[3]), "r"(b0), "r"(b1));
}

// ---------------- prep kernels ----------------
__global__ void prep_x(const float* __restrict__ x) {
    size_t i = ((size_t)blockIdx.x * 256 + threadIdx.x) * 8;
    float4 a0 = *(const float4*)(x + i);
    float4 a1 = *(const float4*)(x + i + 4);
    uint16_t h[8], l[8];
    split1(a0.x, h[0], l[0]); split1(a0.y, h[1], l[1]);
    split1(a0.z, h[2], l[2]); split1(a0.w, h[3], l[3]);
    split1(a1.x, h[4], l[4]); split1(a1.y, h[5], l[5]);
    split1(a1.z, h[6], l[6]); split1(a1.w, h[7], l[7]);
    uint4 hw, lw;
    hw.x = h[0] | ((uint32_t)h[1] << 16); hw.y = h[2] | ((uint32_t)h[3] << 16);
    hw.z = h[4] | ((uint32_t)h[5] << 16); hw.w = h[6] | ((uint32_t)h[7] << 16);
    lw.x = l[0] | ((uint32_t)l[1] << 16); lw.y = l[2] | ((uint32_t)l[3] << 16);
    lw.z = l[4] | ((uint32_t)l[5] << 16); lw.w = l[6] | ((uint32_t)l[7] << 16);
    *(uint4*)(g_x_hi + i) = hw;
    *(uint4*)(g_x_lo + i) = lw;
}
__global__ void prep_wqkv(const float* __restrict__ w) {
    int k = blockIdx.x;          // 0..255
    int n = threadIdx.x;         // 0..767
    uint16_t h, l;
    split1(w[k * 768 + n], h, l);
    g_wq_hi[n * 256 + k] = __ushort_as_bfloat16(h);
    g_wq_lo[n * 256 + k] = __ushort_as_bfloat16(l);
}
__global__ void prep_wout(const float* __restrict__ w) {
    int k = blockIdx.x;          // 0..255
    int n = threadIdx.x;         // 0..255
    uint16_t h, l;
    split1(w[k * 256 + n], h, l);
    g_wo_hi[n * 256 + k] = __ushort_as_bfloat16(h);
    g_wo_lo[n * 256 + k] = __ushort_as_bfloat16(l);
}

// ---------------- split-bf16 GEMM via mma.sync ----------------
// C[Mt,Nt] = Ahi/lo[Mt,256] @ (Whi/lo[Nt,256])^T + bias
// CTA tile 128x128, 8 warps (warp tile 32x64), K chunks of 64.
// smem stride 72 bf16 (144B) -> conflict-free b32 fragment loads.

#define LDA 72
#define SMO_AHI 0
#define SMO_ALO 18432
#define SMO_BHI 36864
#define SMO_BLO 55296
#define SMO_BIAS 73728
#define SMO_TOTAL 74240

__global__ __launch_bounds__(256)
void gemm_mma(const __nv_bfloat16* __restrict__ Ahi,
              const __nv_bfloat16* __restrict__ Alo,
              const __nv_bfloat16* __restrict__ Bhi,
              const __nv_bfloat16* __restrict__ Blo,
              const float* __restrict__ bias,
              float* __restrict__ C,
              int Ntotal, int nN)
{
    extern __shared__ char smem[];
    ushort* sAhi = (ushort*)(smem + SMO_AHI);
    ushort* sAlo = (ushort*)(smem + SMO_ALO);
    ushort* sBhi = (ushort*)(smem + SMO_BHI);
    ushort* sBlo = (ushort*)(smem + SMO_BLO);
    float* sBias = (float*)(smem + SMO_BIAS);
    const uint32_t sb = smem_u32(smem);

    const int tid = threadIdx.x;
    const int m0 = (blockIdx.x / nN) * 128;
    const int n0 = (blockIdx.x % nN) * 128;
    const int wid = tid >> 5, lane = tid & 31;
    const int wm = wid & 3, wn = wid >> 2;      // 4 x 2 warp grid
    const int g = lane >> 2, tig = lane & 3;

    if (tid < 128) sBias[tid] = bias[n0 + tid];

    float c[2][8][4];
    #pragma unroll
    for (int mf = 0; mf < 2; mf++)
        #pragma unroll
        for (int nf = 0; nf < 8; nf++)
            #pragma unroll
            for (int j = 0; j < 4; j++) c[mf][nf][j] = 0.f;

    for (int kc = 0; kc < 4; kc++) {
        // ---- stage A/B hi+lo chunk [128 x 64] via cp.async ----
        #pragma unroll
        for (int it = 0; it < 4; it++) {
            int u = tid + it * 256;             // 0..1023
            int r = u >> 3, f = u & 7;
            size_t goA = (size_t)(m0 + r) * 256 + kc * 64 + f * 8;
            size_t goB = (size_t)(n0 + r) * 256 + kc * 64 + f * 8;
            uint32_t so = (uint32_t)((r * LDA + f * 8) * 2);
            cpasync16(sb + SMO_AHI + so, Ahi + goA);
            cpasync16(sb + SMO_ALO + so, Alo + goA);
            cpasync16(sb + SMO_BHI + so, Bhi + goB);
            cpasync16(sb + SMO_BLO + so, Blo + goB);
        }
        CP_COMMIT();
        CP_WAIT0();
        __syncthreads();

        #pragma unroll
        for (int ks = 0; ks < 4; ks++) {
            const int ck = ks * 16 + tig * 2;
            uint32_t ah[2][4], al[2][4];
            #pragma unroll
            for (int mf = 0; mf < 2; mf++) {
                const ushort* pa = sAhi + (wm * 32 + mf * 16 + g) * LDA + ck;
                ah[mf][0] = *(const uint32_t*)(pa);
                ah[mf][1] = *(const uint32_t*)(pa + 8 * LDA);
                ah[mf][2] = *(const uint32_t*)(pa + 8);
                ah[mf][3] = *(const uint32_t*)(pa + 8 * LDA + 8);
                const ushort* pl = sAlo + (wm * 32 + mf * 16 + g) * LDA + ck;
                al[mf][0] = *(const uint32_t*)(pl);
                al[mf][1] = *(const uint32_t*)(pl + 8 * LDA);
                al[mf][2] = *(const uint32_t*)(pl + 8);
                al[mf][3] = *(const uint32_t*)(pl + 8 * LDA + 8);
            }
            #pragma unroll
            for (int nf = 0; nf < 8; nf++) {
                const int n = wn * 64 + nf * 8 + g;
                const ushort* pb = sBhi + n * LDA + ck;
                uint32_t bh0 = *(const uint32_t*)(pb);
                uint32_t bh1 = *(const uint32_t*)(pb + 8);
                const ushort* pq = sBlo + n * LDA + ck;
                uint32_t bl0 = *(const uint32_t*)(pq);
                uint32_t bl1 = *(const uint32_t*)(pq + 8);
                #pragma unroll
                for (int mf = 0; mf < 2; mf++) {
                    mma16816(c[mf][nf], ah[mf], bh0, bh1);
                    mma16816(c[mf][nf], ah[mf], bl0, bl1);
                    mma16816(c[mf][nf], al[mf], bh0, bh1);
                }
            }
        }
        __syncthreads();
    }

    // ---- epilogue ----
    #pragma unroll
    for (int mf = 0; mf < 2; mf++) {
        int row0 = m0 + wm * 32 + mf * 16 + g;
        #pragma unroll
        for (int nf = 0; nf < 8; nf++) {
            int cl = wn * 64 + nf * 8 + tig * 2;
            float bx = sBias[cl], by = sBias[cl + 1];
            float2 v0 = make_float2(c[mf][nf][0] + bx, c[mf][nf][1] + by);
            float2 v1 = make_float2(c[mf][nf][2] + bx, c[mf][nf][3] + by);
            *(float2*)(C + (size_t)row0 * Ntotal + n0 + cl) = v0;
            *(float2*)(C + (size_t)(row0 + 8) * Ntotal + n0 + cl) = v1;
        }
    }
}

// ---------------- windowed attention (fp32) ----------------
#define AQS 34
#define AKT 52
#define ASS 50

__device__ __forceinline__ u64 splat2(float a) {
    u64 r; asm("mov.b64 %0, {%1, %1};" : "=l"(r) : "f"(a)); return r;
}
__device__ __forceinline__ float2 unpack2(u64 v) {
    float2 f; asm("mov.b64 {%0, %1}, %2;" : "=f"(f.x), "=f"(f.y) : "l"(v)); return f;
}
#define FMA2(d, a, b) asm("fma.rn.f32x2 %0, %1, %2, %0;" : "+l"(d) : "l"(a), "l"(b))

__global__ __launch_bounds__(256)
void attn_kernel(const float* __restrict__ qkv,
                 const float* __restrict__ pos,
                 __nv_bfloat16* __restrict__ Ohi,
                 __nv_bfloat16* __restrict__ Olo)
{
    __shared__ float Q[52 * AQS];
    __shared__ float KT[32 * AKT];
    __shared__ float V[49 * AQS];
    __shared__ float S[49 * ASS];
    __shared__ float POS[170];

    const int tid = threadIdx.x;
    const int win = blockIdx.x;
    const int b = win >> 6, wh = (win >> 3) & 7, ww = win & 7;
    const int ty = tid >> 4, tx = tid & 15;
    const int ty4 = ty * 4, dx = tx * 2;
    const float scl = 5.656854249492381f;   // sqrt(32)

    for (int i = tid; i < 169; i += 256) POS[i] = pos[i];
    const int rowbase = (b * 56 + wh * 7) * 56 + ww * 7;

    for (int h = 0; h < 8; h++) {
        __syncthreads();
        for (int q = tid; q < 784; q += 256) {
            int t = q >> 4, d2 = (q & 15) << 1;
            long row = rowbase + (t / 7) * 56 + (t % 7);
            const float* p = qkv + row * 768 + h * 32 + d2;
            float2 qv = *(const float2*)p;
            float2 kv = *(const float2*)(p + 256);
            float2 vv = *(const float2*)(p + 512);
            *(float2*)(Q + t * AQS + d2) = qv;
            KT[d2 * AKT + t] = kv.x;
            KT[(d2 + 1) * AKT + t] = kv.y;
            *(float2*)(V + t * AQS + d2) = vv;
        }
        __syncthreads();

        if (tid < 169) {
            int sy = tid / 13, sx = tid - sy * 13;
            int r0 = 4 * sy, c0 = 4 * sx;
            u64 sa[4][2];
            #pragma unroll
            for (int i = 0; i < 4; i++) { sa[i][0] = 0ULL; sa[i][1] = 0ULL; }
            #pragma unroll 4
            for (int d = 0; d < 32; d += 2) {
                u64 k0a = *(const u64*)(KT + d * AKT + c0);
                u64 k0b = *(const u64*)(KT + d * AKT + c0 + 2);
                u64 k1a = *(const u64*)(KT + (d + 1) * AKT + c0);
                u64 k1b = *(const u64*)(KT + (d + 1) * AKT + c0 + 2);
                #pragma unroll
                for (int i = 0; i < 4; i++) {
                    float2 qv = *(const float2*)(Q + (r0 + i) * AQS + d);
                    u64 qx = splat2(qv.x), qy = splat2(qv.y);
                    FMA2(sa[i][0], qx, k0a);
                    FMA2(sa[i][1], qx, k0b);
                    FMA2(sa[i][0], qy, k1a);
                    FMA2(sa[i][1], qy, k1b);
                }
            }
            #pragma unroll
            for (int i = 0; i < 4; i++) {
                int r = r0 + i;
                if (r < 49) {
                    int br = r / 7 + r % 7;
                    #pragma unroll
                    for (int jc = 0; jc < 2; jc++) {
                        int cc = c0 + 2 * jc;
                        if (cc <= 48) {
                            float2 f = unpack2(sa[i][jc]);
                            int bc0 = cc / 7 + cc % 7;
                            int bc1 = (cc + 1) / 7 + (cc + 1) % 7;
                            f.x = f.x * scl + POS[br * 13 + bc0];
                            f.y = f.y * scl + POS[br * 13 + bc1];
                            *(float2*)(S + r * ASS + cc) = f;
                        }
                    }
                }
            }
        }
        __syncthreads();

        {
            int warp = tid >> 5, lane = tid & 31;
            for (int r = warp; r < 49; r += 8) {
                float v0 = S[r * ASS + lane];
                float v1 = (lane + 32 < 49) ? S[r * ASS + lane + 32] : -3.0e38f;
                float m = fmaxf(v0, v1);
                #pragma unroll
                for (int off = 16; off > 0; off >>= 1)
                    m = fmaxf(m, __shfl_xor_sync(0xffffffffu, m, off));
                float e0 = __expf(v0 - m);
                float e1 = (lane + 32 < 49) ? __expf(v1 - m) : 0.f;
                float ss = e0 + e1;
                #pragma unroll
                for (int off = 16; off > 0; off >>= 1)
                    ss += __shfl_xor_sync(0xffffffffu, ss, off);
                float inv = 1.f / ss;
                S[r * ASS + lane] = e0 * inv;
                if (lane + 32 < 49) S[r * ASS + lane + 32] = e1 * inv;
            }
        }
        __syncthreads();

        {
            int rr[4];
            #pragma unroll
            for (int i = 0; i < 4; i++) rr[i] = (ty4 + i < 49) ? (ty4 + i) : 0;
            u64 o[4] = {0ULL, 0ULL, 0ULL, 0ULL};
            #pragma unroll 4
            for (int l = 0; l < 48; l += 2) {
                u64 v0 = *(const u64*)(V + l * AQS + dx);
                u64 v1 = *(const u64*)(V + (l + 1) * AQS + dx);
                #pragma unroll
                for (int i = 0; i < 4; i++) {
                    float2 sv = *(const float2*)(S + rr[i] * ASS + l);
                    FMA2(o[i], splat2(sv.x), v0);
                    FMA2(o[i], splat2(sv.y), v1);
                }
            }
            {
                u64 v48 = *(const u64*)(V + 48 * AQS + dx);
                #pragma unroll
                for (int i = 0; i < 4; i++)
                    FMA2(o[i], splat2(S[rr[i] * ASS + 48]), v48);
            }
            #pragma unroll
            for (int i = 0; i < 4; i++) {
                int row = ty4 + i;
                if (row < 49) {
                    long gr = rowbase + (row / 7) * 56 + (row % 7);
                    float2 v = unpack2(o[i]);
                    uint16_t h0, l0, h1, l1;
                    split1(v.x, h0, l0);
                    split1(v.y, h1, l1);
                    *(uint32_t*)(Ohi + gr * 256 + h * 32 + dx) = (uint32_t)h0 | ((uint32_t)h1 << 16);
                    *(uint32_t*)(Olo + gr * 256 + h * 32 + dx) = (uint32_t)l0 | ((uint32_t)l1 << 16);
                }
            }
        }
    }
}

// ---------------- host launcher ----------------
extern "C" void kernel_launch(void* const* d_in, const int* in_sizes, int n_in,
                              void* d_out, int out_size)
{
    const float* x    = (const float*)d_in[0];
    const float* pos  = (const float*)d_in[1];
    const float* wqkv = (const float*)d_in[2];
    const float* bqkv = (const float*)d_in[3];
    const float* wout = (const float*)d_in[4];
    const float* bout = (const float*)d_in[5];
    float* out = (float*)d_out;

    void *p_qkv, *p_xh, *p_xl, *p_oh, *p_ol, *p_wqh, *p_wql, *p_woh, *p_wol;
    cudaGetSymbolAddress(&p_qkv, g_qkv);
    cudaGetSymbolAddress(&p_xh, g_x_hi);
    cudaGetSymbolAddress(&p_xl, g_x_lo);
    cudaGetSymbolAddress(&p_oh, g_o_hi);
    cudaGetSymbolAddress(&p_ol, g_o_lo);
    cudaGetSymbolAddress(&p_wqh, g_wq_hi);
    cudaGetSymbolAddress(&p_wql, g_wq_lo);
    cudaGetSymbolAddress(&p_woh, g_wo_hi);
    cudaGetSymbolAddress(&p_wol, g_wo_lo);

    cudaFuncSetAttribute(gemm_mma, cudaFuncAttributeMaxDynamicSharedMemorySize, SMO_TOTAL);

    prep_x<<<M_TOTAL * 256 / (256 * 8), 256>>>(x);
    prep_wqkv<<<256, 768>>>(wqkv);
    prep_wout<<<256, 256>>>(wout);

    // GEMM1: qkv = x @ w_qkv + b_qkv   (M=200704, N=768)
    gemm_mma<<<(M_TOTAL / 128) * 6, 256, SMO_TOTAL>>>(
        (const __nv_bfloat16*)p_xh, (const __nv_bfloat16*)p_xl,
        (const __nv_bfloat16*)p_wqh, (const __nv_bfloat16*)p_wql,
        bqkv, (float*)p_qkv, 768, 6);

    // windowed attention
    attn_kernel<<<4096, 256>>>((const float*)p_qkv, pos,
                               (__nv_bfloat16*)p_oh, (__nv_bfloat16*)p_ol);

    // GEMM2: out = O @ w_out + b_out (M=200704, N=256)
    gemm_mma<<<(M_TOTAL / 128) * 2, 256, SMO_TOTAL>>>(
        (const __nv_bfloat16*)p_oh, (const __nv_bfloat16*)p_ol,
        (const __nv_bfloat16*)p_woh, (const __nv_bfloat16*)p_wol,
        bout, out, 256, 2);
}